// round 7
// baseline (speedup 1.0000x reference)
#include <cuda_runtime.h>

#define NATOMS 50000
#define INDIM  128
#define HID    256
#define NELEM  4
#define NIMG   500
#define NNZV   2000000
#define NPAD   50304            // 786 * 64 >= NATOMS + 4*63
#define NTILES (NPAD / 64)      // 786
#define OUTSZ  (NIMG + 3 * NATOMS)

// ---------------- device scratch ----------------
// NOTE: these symbols are ONLY referenced inside device code. Passing them as
// kernel arguments from host code passes the HOST shadow address (which GB300
// ATS happily dereferences into host memory) — that was the round 1-5 bug.
__device__ float d_H0[(size_t)NPAD * HID];
__device__ float d_H1[(size_t)NPAD * HID];
__device__ float d_D1[(size_t)NPAD * HID];
__device__ float d_G[(size_t)NATOMS * INDIM];
__device__ float d_W0T[NELEM * HID * INDIM];
__device__ float d_W1T[NELEM * HID * HID];
__device__ int   d_perm[NPAD];
__device__ int   d_cnt[NELEM];
__device__ int   d_cur[NELEM];
__device__ int   d_off[NELEM + 1];
__device__ int   d_is64[2];

__device__ const int*   dp_an;
__device__ const int*   dp_img;
__device__ const int*   dp_rows;
__device__ const int*   dp_cols;
__device__ const float* dp_vals;
__device__ const float* dp_b0;
__device__ const float* dp_b1;
__device__ const float* dp_w2;

__device__ __forceinline__ int ld_idx(const int* __restrict__ p, int i, int is64) {
    return p[is64 ? (2 * i) : i];
}
__device__ __forceinline__ int emap(int z) {
    return z == 1 ? 0 : (z == 6 ? 1 : (z == 8 ? 2 : 3));
}
__device__ __forceinline__ bool in_elem_set(int v) {
    return v == 1 || v == 6 || v == 8 || v == 29;
}

// ---------------- input identification ----------------
// Arguments here are genuine harness device pointers (d_in[...]) — legal.
__global__ void k_detect(const int* pa, const int* pb,
                         const int* q0, const int* q1, const int* q2,
                         const float* r0, const float* r1, const float* r2) {
    __shared__ int s_anfail[2];
    __shared__ int s_isf[3];
    __shared__ int s_qmax[3];
    __shared__ int s_bmax[3];
    int tid = threadIdx.x;
    if (tid < 2) s_anfail[tid] = 0;
    if (tid < 3) { s_isf[tid] = 0; s_qmax[tid] = 0; s_bmax[tid] = 0; }
    __syncthreads();

    const int* pp[2] = {pa, pb};
    const int* qq[3] = {q0, q1, q2};
    const float* rr[3] = {r0, r1, r2};

    if (tid < 32) {
        int c = tid >> 4;
        int i = tid & 15;
        if (!in_elem_set(pp[c][2 * i])) atomicExch(&s_anfail[c], 1);
    }
    for (int j = 0; j < 3; j++) {
        const int* q = qq[j];
        for (int i = tid; i < 1024; i += blockDim.x) {
            int w = q[i];
            if (w < 0 || w > 0x30000000) atomicExch(&s_isf[j], 1);
            atomicMax(&s_qmax[j], w);
        }
    }
    for (int j = 0; j < 3; j++) {
        const float* r = rr[j];
        for (int i = tid; i < 1024; i += blockDim.x) {
            float v = fabsf(r[i]);
            atomicMax(&s_bmax[j], __float_as_int(v));
        }
    }
    __syncthreads();

    if (tid == 0) {
        int asel = s_anfail[0] ? (s_anfail[1] ? 0 : 1) : 0;
        dp_an  = pp[asel];
        dp_img = pp[1 - asel];
        d_is64[0] = (pp[asel][1] == 0 && pp[asel][3] == 0 && pp[asel][5] == 0) ? 1 : 0;

        int vsel = 2;
        if (s_isf[0]) vsel = 0; else if (s_isf[1]) vsel = 1; else if (s_isf[2]) vsel = 2;
        int o1 = (vsel == 0) ? 1 : 0;
        int o2 = (vsel == 2) ? 1 : 2;
        int rsel = (s_qmax[o1] >= s_qmax[o2]) ? o1 : o2;
        int csel = o1 + o2 - rsel;
        dp_vals = (const float*)qq[vsel];
        dp_rows = qq[rsel];
        dp_cols = qq[csel];
        const int* rw = qq[rsel];
        d_is64[1] = (rw[1] == 0 && rw[3] == 0 && rw[5] == 0 && rw[7] == 0 &&
                     rw[9] == 0 && rw[11] == 0) ? 1 : 0;

        // b0 has widest range (+-1/sqrt(128)); dict positional order for b1/W2.
        int b0s;
        if (s_bmax[0] >= s_bmax[1] && s_bmax[0] >= s_bmax[2]) b0s = 0;
        else if (s_bmax[1] >= s_bmax[2]) b0s = 1;
        else b0s = 2;
        int b1s = (b0s + 1) % 3;
        int w2s = (b0s + 2) % 3;
        dp_b0 = rr[b0s]; dp_b1 = rr[b1s]; dp_w2 = rr[w2s];
    }
}

// ---------------- setup kernels ----------------
__global__ void k_zero_out(float* out) {
    for (int i = blockIdx.x * blockDim.x + threadIdx.x; i < OUTSZ;
         i += gridDim.x * blockDim.x)
        out[i] = 0.f;
}

__global__ void k_reset() {
    int i = threadIdx.x;
    if (i < NELEM) { d_cnt[i] = 0; d_cur[i] = 0; }
}

__global__ void k_count() {
    int i = blockIdx.x * blockDim.x + threadIdx.x;
    if (i < NATOMS) atomicAdd(&d_cnt[emap(ld_idx(dp_an, i, d_is64[0]))], 1);
}

__global__ void k_offsets() {
    if (threadIdx.x == 0 && blockIdx.x == 0) {
        int o = 0;
        for (int e = 0; e < NELEM; e++) {
            d_off[e] = o;
            o += ((d_cnt[e] + 63) / 64) * 64;
        }
        d_off[NELEM] = o;
    }
}

__global__ void k_fillperm() {
    int i = blockIdx.x * blockDim.x + threadIdx.x;
    if (i < NPAD) d_perm[i] = -1;
}

__global__ void k_scatter() {
    int i = blockIdx.x * blockDim.x + threadIdx.x;
    if (i < NATOMS) {
        int e = emap(ld_idx(dp_an, i, d_is64[0]));
        int p = atomicAdd(&d_cur[e], 1);
        d_perm[d_off[e] + p] = i;
    }
}

__global__ void k_transpose(const float* __restrict__ W0,
                            const float* __restrict__ W1) {
    const int n0 = NELEM * HID * INDIM;
    const int n1 = NELEM * HID * HID;
    int i = blockIdx.x * blockDim.x + threadIdx.x;
    if (i < n0) {
        int d = i % INDIM;
        int t = i / INDIM;
        int h = t % HID;
        int e = t / HID;
        d_W0T[i] = W0[((size_t)e * INDIM + d) * HID + h];
    } else if (i < n0 + n1) {
        int k = i - n0;
        int i2 = k % HID;
        int t = k / HID;
        int j = t % HID;
        int e = t / HID;
        d_W1T[k] = W1[((size_t)e * HID + i2) * HID + j];
    }
}

// ---------------- tiled fp32 GEMM ----------------
// L=0: H0 = tanh(FP[perm] @ W0 + b0)            (gather, KD=128, ND=256)
// L=1: H1 = tanh(H0 @ W1 + b1)                  (KD=256, ND=256)
// L=2: D0 = (D1 @ W1T) * (1 - H0^2) -> d_H1     (KD=256, ND=256)
// L=3: G[perm[r]] = D0 @ W0T  (scatter)         (KD=256, ND=128)
// All scratch buffers referenced directly in device code; only harness
// pointers (fp / W0 / W1) arrive as arguments.
template <int L>
__global__ __launch_bounds__(256)
void k_gemm(const float* __restrict__ Aarg, const float* __restrict__ Warg) {
    constexpr int KD = (L == 0) ? INDIM : HID;
    constexpr int ND = (L == 3) ? INDIM : HID;

    int row0 = blockIdx.x * 64;
    if (row0 >= d_off[NELEM]) return;
    int e = 0;
#pragma unroll
    for (int t = 0; t < NELEM - 1; t++)
        if (row0 >= d_off[t + 1]) e = t + 1;
    int ncol0 = blockIdx.y * 64;

    const float* A = (L == 0) ? Aarg
                   : (L == 1) ? (const float*)d_H0
                   : (L == 2) ? (const float*)d_D1
                              : (const float*)d_H1;
    const float* Wb = (L <= 1) ? (Warg + (size_t)e * KD * ND)
                    : (L == 2) ? (d_W1T + (size_t)e * HID * HID)
                               : (d_W0T + (size_t)e * HID * INDIM);

    __shared__ float As[16][64];
    __shared__ float Bs[16][64];
    __shared__ int sPerm[64];

    int tid = threadIdx.x;
    if (tid < 64) sPerm[tid] = d_perm[row0 + tid];

    int arow = tid >> 2;
    int ak   = (tid & 3) * 4;
    int bk   = tid >> 4;
    int bn   = (tid & 15) * 4;
    int tm   = tid >> 4;
    int tn   = tid & 15;

    float acc[4][4];
#pragma unroll
    for (int i = 0; i < 4; i++)
#pragma unroll
        for (int j = 0; j < 4; j++) acc[i][j] = 0.f;

    for (int k0 = 0; k0 < KD; k0 += 16) {
        __syncthreads();
        float4 av;
        if (L == 0) {
            int g = sPerm[arow];
            if (g >= 0)
                av = *(const float4*)(A + (size_t)g * KD + k0 + ak);
            else
                av = make_float4(0.f, 0.f, 0.f, 0.f);
        } else {
            av = *(const float4*)(A + (size_t)(row0 + arow) * KD + k0 + ak);
        }
        As[ak + 0][arow] = av.x;
        As[ak + 1][arow] = av.y;
        As[ak + 2][arow] = av.z;
        As[ak + 3][arow] = av.w;

        float4 bv = *(const float4*)(Wb + (size_t)(k0 + bk) * ND + ncol0 + bn);
        *(float4*)&Bs[bk][bn] = bv;
        __syncthreads();

#pragma unroll
        for (int kk = 0; kk < 16; kk++) {
            float a[4], b[4];
#pragma unroll
            for (int i = 0; i < 4; i++) a[i] = As[kk][tm * 4 + i];
#pragma unroll
            for (int j = 0; j < 4; j++) b[j] = Bs[kk][tn * 4 + j];
#pragma unroll
            for (int i = 0; i < 4; i++)
#pragma unroll
                for (int j = 0; j < 4; j++) acc[i][j] += a[i] * b[j];
        }
    }

#pragma unroll
    for (int i = 0; i < 4; i++) {
        int rloc = tm * 4 + i;
        int r = row0 + rloc;
#pragma unroll
        for (int j = 0; j < 4; j++) {
            int c = ncol0 + tn * 4 + j;
            float v = acc[i][j];
            if (L == 0) {
                d_H0[(size_t)r * ND + c] = tanhf(v + dp_b0[e * ND + c]);
            } else if (L == 1) {
                d_H1[(size_t)r * ND + c] = tanhf(v + dp_b1[e * ND + c]);
            } else if (L == 2) {
                float h = d_H0[(size_t)r * ND + c];
                d_H1[(size_t)r * ND + c] = v * (1.f - h * h);
            } else {
                int atom = sPerm[rloc];
                if (atom >= 0) d_G[(size_t)atom * ND + c] = v;
            }
        }
    }
}

// ---------------- layer2: energy + D1 ----------------
__global__ __launch_bounds__(256)
void k_layer2(const float* __restrict__ b2, float* __restrict__ energy) {
    int r = blockIdx.x;
    if (r >= d_off[NELEM]) return;
    int e = 0;
#pragma unroll
    for (int t = 0; t < NELEM - 1; t++)
        if (r >= d_off[t + 1]) e = t + 1;
    int tid = threadIdx.x;

    float h = d_H1[(size_t)r * HID + tid];
    float w = dp_w2[e * HID + tid];
    d_D1[(size_t)r * HID + tid] = w * (1.f - h * h);
    float p = h * w;

    __shared__ float sred[8];
#pragma unroll
    for (int o = 16; o > 0; o >>= 1) p += __shfl_down_sync(0xffffffffu, p, o);
    if ((tid & 31) == 0) sred[tid >> 5] = p;
    __syncthreads();
    if (tid == 0) {
        float s = 0.f;
#pragma unroll
        for (int k = 0; k < 8; k++) s += sred[k];
        int atom = d_perm[r];
        if (atom >= 0)
            atomicAdd(&energy[ld_idx(dp_img, atom, d_is64[0])], s + b2[e]);
    }
}

// ---------------- sparse transpose scatter ----------------
__global__ void k_sparse(float* __restrict__ out) {
    int i = blockIdx.x * blockDim.x + threadIdx.x;
    if (i < NNZV) {
        int is64 = d_is64[1];
        float g = d_G[ld_idx(dp_rows, i, is64)];
        atomicAdd(&out[NIMG + ld_idx(dp_cols, i, is64)], -dp_vals[i] * g);
    }
}

// ---------------- launch ----------------
extern "C" void kernel_launch(void* const* d_in, const int* in_sizes, int n_in,
                              void* d_out, int out_size) {
    int i_fp = 0, i_W0 = 6, i_W1 = 8, i_b2 = 11;
    int p50[2] = {1, 2};
    int p2M[3] = {3, 4, 5};
    int p1k[3] = {7, 9, 10};

    {
        int fp = -1, w0 = -1, w1 = -1, b2p = -1;
        int c50[2], n50 = 0, c2M[3], n2M = 0, c1k[3], n1k = 0;
        for (int i = 0; i < n_in; i++) {
            int s = in_sizes[i];
            if (s == 6400000) fp = i;
            else if (s == 131072) w0 = i;
            else if (s == 262144) w1 = i;
            else if (s == 4) b2p = i;
            else if (s == 50000 || s == 100000) { if (n50 < 2) c50[n50++] = i; }
            else if (s == 2000000 || s == 4000000) { if (n2M < 3) c2M[n2M++] = i; }
            else if (s == 1024) { if (n1k < 3) c1k[n1k++] = i; }
        }
        if (fp >= 0 && w0 >= 0 && w1 >= 0 && b2p >= 0 &&
            n50 == 2 && n2M == 3 && n1k == 3) {
            i_fp = fp; i_W0 = w0; i_W1 = w1; i_b2 = b2p;
            p50[0] = c50[0]; p50[1] = c50[1];
            p2M[0] = c2M[0]; p2M[1] = c2M[1]; p2M[2] = c2M[2];
            p1k[0] = c1k[0]; p1k[1] = c1k[1]; p1k[2] = c1k[2];
        }
    }

    const float* fp = (const float*)d_in[i_fp];
    const float* W0 = (const float*)d_in[i_W0];
    const float* W1 = (const float*)d_in[i_W1];
    const float* b2 = (const float*)d_in[i_b2];
    float* out = (float*)d_out;
    (void)out_size;

    k_detect<<<1, 256>>>((const int*)d_in[p50[0]], (const int*)d_in[p50[1]],
                         (const int*)d_in[p2M[0]], (const int*)d_in[p2M[1]],
                         (const int*)d_in[p2M[2]],
                         (const float*)d_in[p1k[0]], (const float*)d_in[p1k[1]],
                         (const float*)d_in[p1k[2]]);
    k_zero_out<<<512, 256>>>(out);
    k_reset<<<1, 32>>>();
    k_count<<<(NATOMS + 255) / 256, 256>>>();
    k_offsets<<<1, 32>>>();
    k_fillperm<<<(NPAD + 255) / 256, 256>>>();
    k_scatter<<<(NATOMS + 255) / 256, 256>>>();
    {
        int ntr = NELEM * HID * INDIM + NELEM * HID * HID;
        k_transpose<<<(ntr + 255) / 256, 256>>>(W0, W1);
    }

    dim3 gfull(NTILES, HID / 64);   // 786 x 4
    dim3 ghalf(NTILES, INDIM / 64); // 786 x 2

    k_gemm<0><<<gfull, 256>>>(fp, W0);        // H0 = tanh(FP[perm] @ W0 + b0)
    k_gemm<1><<<gfull, 256>>>(nullptr, W1);   // H1 = tanh(H0 @ W1 + b1)
    k_layer2<<<NPAD, 256>>>(b2, out);         // energy + D1
    k_gemm<2><<<gfull, 256>>>(nullptr, nullptr); // D0 = (D1 @ W1T)*(1-H0^2)
    k_gemm<3><<<ghalf, 256>>>(nullptr, nullptr); // G = D0 @ W0T (scatter)
    k_sparse<<<(NNZV + 255) / 256, 256>>>(out);  // forces
}

// round 8
// speedup vs baseline: 1.0804x; 1.0804x over previous
#include <cuda_runtime.h>
#include <cstdint>

#define NATOMS 50000
#define INDIM  128
#define HID    256
#define NELEM  4
#define NIMG   500
#define NNZV   2000000
#define NPAD   50560            // 395 * 128 >= NATOMS + 4*127
#define NT128  (NPAD / 128)     // 395
#define OUTSZ  (NIMG + 3 * NATOMS)

// ---------------- device scratch (referenced ONLY in device code) ----------
__device__ float d_H0[(size_t)NPAD * HID];
__device__ float d_H1[(size_t)NPAD * HID];   // later reused for D0
__device__ float d_D1[(size_t)NPAD * HID];
__device__ float d_G[(size_t)NATOMS * INDIM];
__device__ float d_W0T[NELEM * HID * INDIM]; // [e][h][d]
__device__ float d_W1T[NELEM * HID * HID];   // [e][j][i]
__device__ int   d_perm[NPAD];
__device__ int   d_cnt[NELEM];
__device__ int   d_cur[NELEM];
__device__ int   d_off[NELEM + 1];
__device__ int   d_is64[2];

__device__ const int*   dp_an;
__device__ const int*   dp_img;
__device__ const int*   dp_rows;
__device__ const int*   dp_cols;
__device__ const float* dp_vals;
__device__ const float* dp_b0;
__device__ const float* dp_b1;
__device__ const float* dp_w2;

__device__ __forceinline__ int ld_idx(const int* __restrict__ p, int i, int is64) {
    return p[is64 ? (2 * i) : i];
}
__device__ __forceinline__ int emap(int z) {
    return z == 1 ? 0 : (z == 6 ? 1 : (z == 8 ? 2 : 3));
}
__device__ __forceinline__ bool in_elem_set(int v) {
    return v == 1 || v == 6 || v == 8 || v == 29;
}
__device__ __forceinline__ float to_tf32(float x) {
    float r;
    asm("cvt.rna.tf32.f32 %0, %1;" : "=f"(r) : "f"(x));
    return r;
}
__device__ __forceinline__ void mma8(float* c, const unsigned* a,
                                     unsigned b0, unsigned b1) {
    asm volatile(
        "mma.sync.aligned.m16n8k8.row.col.f32.tf32.tf32.f32 "
        "{%0,%1,%2,%3}, {%4,%5,%6,%7}, {%8,%9}, {%0,%1,%2,%3};"
        : "+f"(c[0]), "+f"(c[1]), "+f"(c[2]), "+f"(c[3])
        : "r"(a[0]), "r"(a[1]), "r"(a[2]), "r"(a[3]), "r"(b0), "r"(b1));
}

// ---------------- input identification ----------------
__global__ void k_detect(const int* pa, const int* pb,
                         const int* q0, const int* q1, const int* q2,
                         const float* r0, const float* r1, const float* r2) {
    __shared__ int s_anfail[2];
    __shared__ int s_isf[3];
    __shared__ int s_qmax[3];
    __shared__ int s_bmax[3];
    int tid = threadIdx.x;
    if (tid < 2) s_anfail[tid] = 0;
    if (tid < 3) { s_isf[tid] = 0; s_qmax[tid] = 0; s_bmax[tid] = 0; }
    __syncthreads();

    const int* pp[2] = {pa, pb};
    const int* qq[3] = {q0, q1, q2};
    const float* rr[3] = {r0, r1, r2};

    if (tid < 32) {
        int c = tid >> 4;
        int i = tid & 15;
        if (!in_elem_set(pp[c][2 * i])) atomicExch(&s_anfail[c], 1);
    }
    for (int j = 0; j < 3; j++) {
        const int* q = qq[j];
        for (int i = tid; i < 1024; i += blockDim.x) {
            int w = q[i];
            if (w < 0 || w > 0x30000000) atomicExch(&s_isf[j], 1);
            atomicMax(&s_qmax[j], w);
        }
    }
    for (int j = 0; j < 3; j++) {
        const float* r = rr[j];
        for (int i = tid; i < 1024; i += blockDim.x) {
            float v = fabsf(r[i]);
            atomicMax(&s_bmax[j], __float_as_int(v));
        }
    }
    __syncthreads();

    if (tid == 0) {
        int asel = s_anfail[0] ? (s_anfail[1] ? 0 : 1) : 0;
        dp_an  = pp[asel];
        dp_img = pp[1 - asel];
        d_is64[0] = (pp[asel][1] == 0 && pp[asel][3] == 0 && pp[asel][5] == 0) ? 1 : 0;

        int vsel = 2;
        if (s_isf[0]) vsel = 0; else if (s_isf[1]) vsel = 1; else if (s_isf[2]) vsel = 2;
        int o1 = (vsel == 0) ? 1 : 0;
        int o2 = (vsel == 2) ? 1 : 2;
        int rsel = (s_qmax[o1] >= s_qmax[o2]) ? o1 : o2;
        int csel = o1 + o2 - rsel;
        dp_vals = (const float*)qq[vsel];
        dp_rows = qq[rsel];
        dp_cols = qq[csel];
        const int* rw = qq[rsel];
        d_is64[1] = (rw[1] == 0 && rw[3] == 0 && rw[5] == 0 && rw[7] == 0 &&
                     rw[9] == 0 && rw[11] == 0) ? 1 : 0;

        int b0s;
        if (s_bmax[0] >= s_bmax[1] && s_bmax[0] >= s_bmax[2]) b0s = 0;
        else if (s_bmax[1] >= s_bmax[2]) b0s = 1;
        else b0s = 2;
        int b1s = (b0s + 1) % 3;
        int w2s = (b0s + 2) % 3;
        dp_b0 = rr[b0s]; dp_b1 = rr[b1s]; dp_w2 = rr[w2s];
    }
}

// ---------------- setup kernels ----------------
__global__ void k_zero_out(float* out) {
    for (int i = blockIdx.x * blockDim.x + threadIdx.x; i < OUTSZ;
         i += gridDim.x * blockDim.x)
        out[i] = 0.f;
}

__global__ void k_reset() {
    int i = threadIdx.x;
    if (i < NELEM) { d_cnt[i] = 0; d_cur[i] = 0; }
}

__global__ void k_count() {
    __shared__ int sc[NELEM];
    int tid = threadIdx.x;
    if (tid < NELEM) sc[tid] = 0;
    __syncthreads();
    int i = blockIdx.x * blockDim.x + tid;
    if (i < NATOMS) atomicAdd(&sc[emap(ld_idx(dp_an, i, d_is64[0]))], 1);
    __syncthreads();
    if (tid < NELEM && sc[tid] > 0) atomicAdd(&d_cnt[tid], sc[tid]);
}

__global__ void k_offsets() {
    if (threadIdx.x == 0 && blockIdx.x == 0) {
        int o = 0;
        for (int e = 0; e < NELEM; e++) {
            d_off[e] = o;
            o += ((d_cnt[e] + 127) / 128) * 128;
        }
        d_off[NELEM] = o;
    }
}

__global__ void k_fillperm() {
    int i = blockIdx.x * blockDim.x + threadIdx.x;
    if (i < NPAD) d_perm[i] = -1;
}

__global__ void k_scatter() {
    __shared__ int lc[NELEM], base[NELEM];
    int tid = threadIdx.x;
    if (tid < NELEM) lc[tid] = 0;
    __syncthreads();
    int i = blockIdx.x * blockDim.x + tid;
    int e = -1, rank = 0;
    if (i < NATOMS) {
        e = emap(ld_idx(dp_an, i, d_is64[0]));
        rank = atomicAdd(&lc[e], 1);
    }
    __syncthreads();
    if (tid < NELEM && lc[tid] > 0) base[tid] = atomicAdd(&d_cur[tid], lc[tid]);
    __syncthreads();
    if (i < NATOMS) d_perm[d_off[e] + base[e] + rank] = i;
}

__global__ void k_transpose(const float* __restrict__ W0,
                            const float* __restrict__ W1) {
    const int n0 = NELEM * HID * INDIM;
    const int n1 = NELEM * HID * HID;
    int i = blockIdx.x * blockDim.x + threadIdx.x;
    if (i < n0) {
        int d = i % INDIM;
        int t = i / INDIM;
        int h = t % HID;
        int e = t / HID;
        d_W0T[i] = W0[((size_t)e * INDIM + d) * HID + h];
    } else if (i < n0 + n1) {
        int k = i - n0;
        int i2 = k % HID;
        int t = k / HID;
        int j = t % HID;
        int e = t / HID;
        d_W1T[k] = W1[((size_t)e * HID + i2) * HID + j];
    }
}

// ---------------- TF32x3 tensor-core GEMM ----------------
// Block 128 rows x 128 cols, 8 warps (4 m-groups x 2 n-groups), warp 32x64.
// BK=16, mma.m16n8k8, 3 passes (hi*hi, hi*lo, lo*hi) for ~fp32 accuracy.
// L=0: H0 = tanh(FP[perm] @ W0 + b0)        KD=128 ND=256
// L=1: H1 = tanh(H0 @ W1 + b1)              KD=256 ND=256
// L=2: D0 = (D1 @ W1T) * (1 - H0^2) -> d_H1 KD=256 ND=256
// L=3: G[perm[r]] = D0 @ W0T (scatter)      KD=256 ND=128
#define SA 20     // As row stride (floats): conflict-free frag loads
#define SB 136    // Bs row stride (floats): conflict-free frag loads

template <int L>
__global__ __launch_bounds__(256)
void k_gemm_tc(const float* __restrict__ Aarg, const float* __restrict__ Warg) {
    constexpr int KD = (L == 0) ? INDIM : HID;
    constexpr int ND = (L == 3) ? INDIM : HID;

    const int row0 = blockIdx.x * 128;
    if (row0 >= d_off[NELEM]) return;
    int e = 0;
#pragma unroll
    for (int t = 0; t < NELEM - 1; t++)
        if (row0 >= d_off[t + 1]) e = t + 1;
    const int ncol0 = blockIdx.y * 128;

    __shared__ float As_hi[128][SA], As_lo[128][SA];
    __shared__ float Bs_hi[16][SB],  Bs_lo[16][SB];
    __shared__ int sPerm[128];

    const int tid  = threadIdx.x;
    const int lane = tid & 31;
    const int wid  = tid >> 5;
    const int wm   = wid & 3;        // 0..3 -> rows wm*32
    const int wn   = wid >> 2;       // 0..1 -> cols wn*64

    if (tid < 128) sPerm[tid] = d_perm[row0 + tid];

    const float* A = (L == 0) ? Aarg
                   : (L == 1) ? (const float*)d_H0
                   : (L == 2) ? (const float*)d_D1
                              : (const float*)d_H1;
    const float* Wb = (L <= 1) ? (Warg + (size_t)e * KD * ND)
                    : (L == 2) ? (d_W1T + (size_t)e * HID * HID)
                               : (d_W0T + (size_t)e * HID * INDIM);

    float acc[2][8][4];
#pragma unroll
    for (int mt = 0; mt < 2; mt++)
#pragma unroll
        for (int nt = 0; nt < 8; nt++)
#pragma unroll
            for (int j = 0; j < 4; j++) acc[mt][nt][j] = 0.f;

    const int arow = tid >> 1;           // 0..127
    const int akk  = (tid & 1) * 8;      // 0 or 8
    const int bkr  = tid >> 4;           // 0..15
    const int bnb  = (tid & 15) * 4;     // 0..60

    for (int k0 = 0; k0 < KD; k0 += 16) {
        __syncthreads();
        // ---- fill A (128 x 16) hi/lo ----
        {
            const float* src;
            bool valid = true;
            if (L == 0) {
                int g = sPerm[arow];
                valid = (g >= 0);
                src = A + (size_t)(valid ? g : 0) * KD + k0 + akk;
            } else {
                src = A + (size_t)(row0 + arow) * KD + k0 + akk;
            }
#pragma unroll
            for (int j = 0; j < 2; j++) {
                float4 v = valid ? *(const float4*)(src + 4 * j)
                                 : make_float4(0.f, 0.f, 0.f, 0.f);
                float4 hv, lv;
                hv.x = to_tf32(v.x); lv.x = v.x - hv.x;
                hv.y = to_tf32(v.y); lv.y = v.y - hv.y;
                hv.z = to_tf32(v.z); lv.z = v.z - hv.z;
                hv.w = to_tf32(v.w); lv.w = v.w - hv.w;
                *(float4*)&As_hi[arow][akk + 4 * j] = hv;
                *(float4*)&As_lo[arow][akk + 4 * j] = lv;
            }
        }
        // ---- fill B (16 x 128) hi/lo ----
        {
            const float* src = Wb + (size_t)(k0 + bkr) * ND + ncol0 + bnb;
#pragma unroll
            for (int j = 0; j < 2; j++) {
                float4 v = *(const float4*)(src + 64 * j);
                float4 hv, lv;
                hv.x = to_tf32(v.x); lv.x = v.x - hv.x;
                hv.y = to_tf32(v.y); lv.y = v.y - hv.y;
                hv.z = to_tf32(v.z); lv.z = v.z - hv.z;
                hv.w = to_tf32(v.w); lv.w = v.w - hv.w;
                *(float4*)&Bs_hi[bkr][bnb + 64 * j] = hv;
                *(float4*)&Bs_lo[bkr][bnb + 64 * j] = lv;
            }
        }
        __syncthreads();

#pragma unroll
        for (int ks = 0; ks < 2; ks++) {
            unsigned ah[2][4], al[2][4];
#pragma unroll
            for (int mt = 0; mt < 2; mt++) {
                int m  = wm * 32 + mt * 16 + (lane >> 2);
                int kk = ks * 8 + (lane & 3);
                ah[mt][0] = __float_as_uint(As_hi[m][kk]);
                ah[mt][1] = __float_as_uint(As_hi[m + 8][kk]);
                ah[mt][2] = __float_as_uint(As_hi[m][kk + 4]);
                ah[mt][3] = __float_as_uint(As_hi[m + 8][kk + 4]);
                al[mt][0] = __float_as_uint(As_lo[m][kk]);
                al[mt][1] = __float_as_uint(As_lo[m + 8][kk]);
                al[mt][2] = __float_as_uint(As_lo[m][kk + 4]);
                al[mt][3] = __float_as_uint(As_lo[m + 8][kk + 4]);
            }
#pragma unroll
            for (int nt = 0; nt < 8; nt++) {
                int n  = wn * 64 + nt * 8 + (lane >> 2);
                int kb = ks * 8 + (lane & 3);
                unsigned bh0 = __float_as_uint(Bs_hi[kb][n]);
                unsigned bh1 = __float_as_uint(Bs_hi[kb + 4][n]);
                unsigned bl0 = __float_as_uint(Bs_lo[kb][n]);
                unsigned bl1 = __float_as_uint(Bs_lo[kb + 4][n]);
#pragma unroll
                for (int mt = 0; mt < 2; mt++) {
                    mma8(acc[mt][nt], ah[mt], bh0, bh1);  // hi*hi
                    mma8(acc[mt][nt], ah[mt], bl0, bl1);  // hi*lo
                    mma8(acc[mt][nt], al[mt], bh0, bh1);  // lo*hi
                }
            }
        }
    }

    // ---- epilogue ----
#pragma unroll
    for (int mt = 0; mt < 2; mt++) {
#pragma unroll
        for (int nt = 0; nt < 8; nt++) {
            float* cc = acc[mt][nt];
            int rloc = wm * 32 + mt * 16 + (lane >> 2);
            int c = ncol0 + wn * 64 + nt * 8 + (lane & 3) * 2;
            if (L == 0) {
                float2 b = *(const float2*)&dp_b0[e * ND + c];
                size_t r0i = (size_t)(row0 + rloc) * ND + c;
                size_t r1i = (size_t)(row0 + rloc + 8) * ND + c;
                d_H0[r0i]     = tanhf(cc[0] + b.x);
                d_H0[r0i + 1] = tanhf(cc[1] + b.y);
                d_H0[r1i]     = tanhf(cc[2] + b.x);
                d_H0[r1i + 1] = tanhf(cc[3] + b.y);
            } else if (L == 1) {
                float2 b = *(const float2*)&dp_b1[e * ND + c];
                size_t r0i = (size_t)(row0 + rloc) * ND + c;
                size_t r1i = (size_t)(row0 + rloc + 8) * ND + c;
                d_H1[r0i]     = tanhf(cc[0] + b.x);
                d_H1[r0i + 1] = tanhf(cc[1] + b.y);
                d_H1[r1i]     = tanhf(cc[2] + b.x);
                d_H1[r1i + 1] = tanhf(cc[3] + b.y);
            } else if (L == 2) {
                size_t r0i = (size_t)(row0 + rloc) * ND + c;
                size_t r1i = (size_t)(row0 + rloc + 8) * ND + c;
                float2 h0 = *(const float2*)&d_H0[r0i];
                float2 h1 = *(const float2*)&d_H0[r1i];
                d_H1[r0i]     = cc[0] * (1.f - h0.x * h0.x);
                d_H1[r0i + 1] = cc[1] * (1.f - h0.y * h0.y);
                d_H1[r1i]     = cc[2] * (1.f - h1.x * h1.x);
                d_H1[r1i + 1] = cc[3] * (1.f - h1.y * h1.y);
            } else {
                int a0 = sPerm[rloc];
                int a1 = sPerm[rloc + 8];
                if (a0 >= 0) {
                    d_G[(size_t)a0 * ND + c]     = cc[0];
                    d_G[(size_t)a0 * ND + c + 1] = cc[1];
                }
                if (a1 >= 0) {
                    d_G[(size_t)a1 * ND + c]     = cc[2];
                    d_G[(size_t)a1 * ND + c + 1] = cc[3];
                }
            }
        }
    }
}

// ---------------- layer2: energy + D1 ----------------
__global__ __launch_bounds__(256)
void k_layer2(const float* __restrict__ b2, float* __restrict__ energy) {
    int r = blockIdx.x;
    if (r >= d_off[NELEM]) return;
    int e = 0;
#pragma unroll
    for (int t = 0; t < NELEM - 1; t++)
        if (r >= d_off[t + 1]) e = t + 1;
    int tid = threadIdx.x;

    float h = d_H1[(size_t)r * HID + tid];
    float w = dp_w2[e * HID + tid];
    d_D1[(size_t)r * HID + tid] = w * (1.f - h * h);
    float p = h * w;

    __shared__ float sred[8];
#pragma unroll
    for (int o = 16; o > 0; o >>= 1) p += __shfl_down_sync(0xffffffffu, p, o);
    if ((tid & 31) == 0) sred[tid >> 5] = p;
    __syncthreads();
    if (tid == 0) {
        float s = 0.f;
#pragma unroll
        for (int k = 0; k < 8; k++) s += sred[k];
        int atom = d_perm[r];
        if (atom >= 0)
            atomicAdd(&energy[ld_idx(dp_img, atom, d_is64[0])], s + b2[e]);
    }
}

// ---------------- sparse transpose scatter ----------------
__global__ void k_sparse(float* __restrict__ out) {
    int i = blockIdx.x * blockDim.x + threadIdx.x;
    if (i < NNZV) {
        int is64 = d_is64[1];
        float g = d_G[ld_idx(dp_rows, i, is64)];
        atomicAdd(&out[NIMG + ld_idx(dp_cols, i, is64)], -dp_vals[i] * g);
    }
}

// ---------------- launch ----------------
extern "C" void kernel_launch(void* const* d_in, const int* in_sizes, int n_in,
                              void* d_out, int out_size) {
    int i_fp = 0, i_W0 = 6, i_W1 = 8, i_b2 = 11;
    int p50[2] = {1, 2};
    int p2M[3] = {3, 4, 5};
    int p1k[3] = {7, 9, 10};

    {
        int fp = -1, w0 = -1, w1 = -1, b2p = -1;
        int c50[2], n50 = 0, c2M[3], n2M = 0, c1k[3], n1k = 0;
        for (int i = 0; i < n_in; i++) {
            int s = in_sizes[i];
            if (s == 6400000) fp = i;
            else if (s == 131072) w0 = i;
            else if (s == 262144) w1 = i;
            else if (s == 4) b2p = i;
            else if (s == 50000 || s == 100000) { if (n50 < 2) c50[n50++] = i; }
            else if (s == 2000000 || s == 4000000) { if (n2M < 3) c2M[n2M++] = i; }
            else if (s == 1024) { if (n1k < 3) c1k[n1k++] = i; }
        }
        if (fp >= 0 && w0 >= 0 && w1 >= 0 && b2p >= 0 &&
            n50 == 2 && n2M == 3 && n1k == 3) {
            i_fp = fp; i_W0 = w0; i_W1 = w1; i_b2 = b2p;
            p50[0] = c50[0]; p50[1] = c50[1];
            p2M[0] = c2M[0]; p2M[1] = c2M[1]; p2M[2] = c2M[2];
            p1k[0] = c1k[0]; p1k[1] = c1k[1]; p1k[2] = c1k[2];
        }
    }

    const float* fp = (const float*)d_in[i_fp];
    const float* W0 = (const float*)d_in[i_W0];
    const float* W1 = (const float*)d_in[i_W1];
    const float* b2 = (const float*)d_in[i_b2];
    float* out = (float*)d_out;
    (void)out_size;

    k_detect<<<1, 256>>>((const int*)d_in[p50[0]], (const int*)d_in[p50[1]],
                         (const int*)d_in[p2M[0]], (const int*)d_in[p2M[1]],
                         (const int*)d_in[p2M[2]],
                         (const float*)d_in[p1k[0]], (const float*)d_in[p1k[1]],
                         (const float*)d_in[p1k[2]]);
    k_zero_out<<<512, 256>>>(out);
    k_reset<<<1, 32>>>();
    k_count<<<(NATOMS + 255) / 256, 256>>>();
    k_offsets<<<1, 32>>>();
    k_fillperm<<<(NPAD + 255) / 256, 256>>>();
    k_scatter<<<(NATOMS + 255) / 256, 256>>>();
    {
        int ntr = NELEM * HID * INDIM + NELEM * HID * HID;
        k_transpose<<<(ntr + 255) / 256, 256>>>(W0, W1);
    }

    dim3 gfull(NT128, 2);   // 395 x 2 (ND=256)
    dim3 ghalf(NT128, 1);   // 395 x 1 (ND=128)

    k_gemm_tc<0><<<gfull, 256>>>(fp, W0);         // H0
    k_gemm_tc<1><<<gfull, 256>>>(nullptr, W1);    // H1
    k_layer2<<<NPAD, 256>>>(b2, out);             // energy + D1
    k_gemm_tc<2><<<gfull, 256>>>(nullptr, nullptr); // D0
    k_gemm_tc<3><<<ghalf, 256>>>(nullptr, nullptr); // G scatter
    k_sparse<<<(NNZV + 255) / 256, 256>>>(out);     // forces
}

// round 9
// speedup vs baseline: 1.6859x; 1.5605x over previous
#include <cuda_runtime.h>
#include <cuda_bf16.h>
#include <cstdint>

#define NATOMS 50000
#define INDIM  128
#define HID    256
#define NELEM  4
#define NIMG   500
#define NNZV   2000000
#define NPAD   50560            // 395 * 128 >= NATOMS + 4*127
#define NT128  (NPAD / 128)     // 395
#define OUTSZ  (NIMG + 3 * NATOMS)

// ---------------- device scratch (referenced ONLY in device code) ----------
__device__ float d_H0[(size_t)NPAD * HID];
__device__ float d_H1[(size_t)NPAD * HID];   // later reused for D0
__device__ float d_D1[(size_t)NPAD * HID];
__device__ float d_G[(size_t)NATOMS * INDIM];
__device__ float d_W0T[NELEM * HID * INDIM]; // [e][h][d]
__device__ float d_W1T[NELEM * HID * HID];   // [e][j][i]
__device__ int   d_perm[NPAD];
__device__ int   d_cnt[NELEM];
__device__ int   d_cur[NELEM];
__device__ int   d_off[NELEM + 1];
__device__ int   d_is64[2];

__device__ const int*   dp_an;
__device__ const int*   dp_img;
__device__ const int*   dp_rows;
__device__ const int*   dp_cols;
__device__ const float* dp_vals;
__device__ const float* dp_b0;
__device__ const float* dp_b1;
__device__ const float* dp_w2;

__device__ __forceinline__ int ld_idx(const int* __restrict__ p, int i, int is64) {
    return p[is64 ? (2 * i) : i];
}
__device__ __forceinline__ int emap(int z) {
    return z == 1 ? 0 : (z == 6 ? 1 : (z == 8 ? 2 : 3));
}
__device__ __forceinline__ bool in_elem_set(int v) {
    return v == 1 || v == 6 || v == 8 || v == 29;
}

// pack two floats as bf16x2 (x in low half)
__device__ __forceinline__ unsigned bpack(float x, float y) {
    __nv_bfloat162 t = __floats2bfloat162_rn(x, y);
    return *reinterpret_cast<unsigned*>(&t);
}
// hi/lo bf16 split of a float pair
__device__ __forceinline__ void split_pair(float x, float y,
                                           unsigned& hi, unsigned& lo) {
    float hx = __bfloat162float(__float2bfloat16(x));
    float hy = __bfloat162float(__float2bfloat16(y));
    hi = bpack(hx, hy);
    lo = bpack(x - hx, y - hy);
}
__device__ __forceinline__ void mma16(float* c, const unsigned* a,
                                      unsigned b0, unsigned b1) {
    asm volatile(
        "mma.sync.aligned.m16n8k16.row.col.f32.bf16.bf16.f32 "
        "{%0,%1,%2,%3}, {%4,%5,%6,%7}, {%8,%9}, {%0,%1,%2,%3};"
        : "+f"(c[0]), "+f"(c[1]), "+f"(c[2]), "+f"(c[3])
        : "r"(a[0]), "r"(a[1]), "r"(a[2]), "r"(a[3]), "r"(b0), "r"(b1));
}

// ---------------- input identification ----------------
__global__ void k_detect(const int* pa, const int* pb,
                         const int* q0, const int* q1, const int* q2,
                         const float* r0, const float* r1, const float* r2) {
    __shared__ int s_anfail[2];
    __shared__ int s_isf[3];
    __shared__ int s_qmax[3];
    __shared__ int s_bmax[3];
    int tid = threadIdx.x;
    if (tid < 2) s_anfail[tid] = 0;
    if (tid < 3) { s_isf[tid] = 0; s_qmax[tid] = 0; s_bmax[tid] = 0; }
    __syncthreads();

    const int* pp[2] = {pa, pb};
    const int* qq[3] = {q0, q1, q2};
    const float* rr[3] = {r0, r1, r2};

    if (tid < 32) {
        int c = tid >> 4;
        int i = tid & 15;
        if (!in_elem_set(pp[c][2 * i])) atomicExch(&s_anfail[c], 1);
    }
    for (int j = 0; j < 3; j++) {
        const int* q = qq[j];
        for (int i = tid; i < 1024; i += blockDim.x) {
            int w = q[i];
            if (w < 0 || w > 0x30000000) atomicExch(&s_isf[j], 1);
            atomicMax(&s_qmax[j], w);
        }
    }
    for (int j = 0; j < 3; j++) {
        const float* r = rr[j];
        for (int i = tid; i < 1024; i += blockDim.x) {
            float v = fabsf(r[i]);
            atomicMax(&s_bmax[j], __float_as_int(v));
        }
    }
    __syncthreads();

    if (tid == 0) {
        int asel = s_anfail[0] ? (s_anfail[1] ? 0 : 1) : 0;
        dp_an  = pp[asel];
        dp_img = pp[1 - asel];
        d_is64[0] = (pp[asel][1] == 0 && pp[asel][3] == 0 && pp[asel][5] == 0) ? 1 : 0;

        int vsel = 2;
        if (s_isf[0]) vsel = 0; else if (s_isf[1]) vsel = 1; else if (s_isf[2]) vsel = 2;
        int o1 = (vsel == 0) ? 1 : 0;
        int o2 = (vsel == 2) ? 1 : 2;
        int rsel = (s_qmax[o1] >= s_qmax[o2]) ? o1 : o2;
        int csel = o1 + o2 - rsel;
        dp_vals = (const float*)qq[vsel];
        dp_rows = qq[rsel];
        dp_cols = qq[csel];
        const int* rw = qq[rsel];
        d_is64[1] = (rw[1] == 0 && rw[3] == 0 && rw[5] == 0 && rw[7] == 0 &&
                     rw[9] == 0 && rw[11] == 0) ? 1 : 0;

        int b0s;
        if (s_bmax[0] >= s_bmax[1] && s_bmax[0] >= s_bmax[2]) b0s = 0;
        else if (s_bmax[1] >= s_bmax[2]) b0s = 1;
        else b0s = 2;
        int b1s = (b0s + 1) % 3;
        int w2s = (b0s + 2) % 3;
        dp_b0 = rr[b0s]; dp_b1 = rr[b1s]; dp_w2 = rr[w2s];
    }
}

// ---------------- setup kernels ----------------
__global__ void k_zero_out(float* out) {
    for (int i = blockIdx.x * blockDim.x + threadIdx.x; i < OUTSZ;
         i += gridDim.x * blockDim.x)
        out[i] = 0.f;
}

__global__ void k_reset() {
    int i = threadIdx.x;
    if (i < NELEM) { d_cnt[i] = 0; d_cur[i] = 0; }
}

__global__ void k_count() {
    __shared__ int sc[NELEM];
    int tid = threadIdx.x;
    if (tid < NELEM) sc[tid] = 0;
    __syncthreads();
    int i = blockIdx.x * blockDim.x + tid;
    if (i < NATOMS) atomicAdd(&sc[emap(ld_idx(dp_an, i, d_is64[0]))], 1);
    __syncthreads();
    if (tid < NELEM && sc[tid] > 0) atomicAdd(&d_cnt[tid], sc[tid]);
}

__global__ void k_offsets() {
    if (threadIdx.x == 0 && blockIdx.x == 0) {
        int o = 0;
        for (int e = 0; e < NELEM; e++) {
            d_off[e] = o;
            o += ((d_cnt[e] + 127) / 128) * 128;
        }
        d_off[NELEM] = o;
    }
}

__global__ void k_fillperm() {
    int i = blockIdx.x * blockDim.x + threadIdx.x;
    if (i < NPAD) d_perm[i] = -1;
}

__global__ void k_scatter() {
    __shared__ int lc[NELEM], base[NELEM];
    int tid = threadIdx.x;
    if (tid < NELEM) lc[tid] = 0;
    __syncthreads();
    int i = blockIdx.x * blockDim.x + tid;
    int e = -1, rank = 0;
    if (i < NATOMS) {
        e = emap(ld_idx(dp_an, i, d_is64[0]));
        rank = atomicAdd(&lc[e], 1);
    }
    __syncthreads();
    if (tid < NELEM && lc[tid] > 0) base[tid] = atomicAdd(&d_cur[tid], lc[tid]);
    __syncthreads();
    if (i < NATOMS) d_perm[d_off[e] + base[e] + rank] = i;
}

__global__ void k_transpose(const float* __restrict__ W0,
                            const float* __restrict__ W1) {
    const int n0 = NELEM * HID * INDIM;
    const int n1 = NELEM * HID * HID;
    int i = blockIdx.x * blockDim.x + threadIdx.x;
    if (i < n0) {
        int d = i % INDIM;
        int t = i / INDIM;
        int h = t % HID;
        int e = t / HID;
        d_W0T[i] = W0[((size_t)e * INDIM + d) * HID + h];
    } else if (i < n0 + n1) {
        int k = i - n0;
        int i2 = k % HID;
        int t = k / HID;
        int j = t % HID;
        int e = t / HID;
        d_W1T[k] = W1[((size_t)e * HID + i2) * HID + j];
    }
}

// ---------------- BF16x3 tensor-core GEMM (mma.m16n8k16) ----------------
// Block 128 rows x 128 cols, 8 warps (4 m x 2 n), warp tile 32x64, BK=16.
// 3 passes: hi*hi + hi*lo + lo*hi  (~17-bit effective mantissa).
// L=0: H0 = tanh(FP[perm] @ W0 + b0)        KD=128 ND=256
// L=1: H1 = tanh(H0 @ W1 + b1)              KD=256 ND=256
// L=2: D0 = (D1 @ W1T) * (1 - H0^2) -> d_H1 KD=256 ND=256
// L=3: G[perm[r]] = D0 @ W0T (scatter)      KD=256 ND=128
#define SAN 20    // As u32 row stride (conflict-free frag loads)
#define SBN 136   // Bs u32 row stride (conflict-free frag loads)

template <int L>
__global__ __launch_bounds__(256)
void k_gemm_tc(const float* __restrict__ Aarg, const float* __restrict__ Warg) {
    constexpr int KD = (L == 0) ? INDIM : HID;
    constexpr int ND = (L == 3) ? INDIM : HID;

    const int row0 = blockIdx.x * 128;
    if (row0 >= d_off[NELEM]) return;
    int e = 0;
#pragma unroll
    for (int t = 0; t < NELEM - 1; t++)
        if (row0 >= d_off[t + 1]) e = t + 1;
    const int ncol0 = blockIdx.y * 128;

    // u32 = bf16x2 along k (even k in low half)
    __shared__ unsigned As_hi[128][SAN], As_lo[128][SAN];
    __shared__ unsigned Bs_hi[8][SBN],  Bs_lo[8][SBN];
    __shared__ int sPerm[128];

    const int tid  = threadIdx.x;
    const int lane = tid & 31;
    const int wid  = tid >> 5;
    const int wm   = wid & 3;        // rows wm*32
    const int wn   = wid >> 2;       // cols wn*64

    if (tid < 128) sPerm[tid] = d_perm[row0 + tid];

    const float* A = (L == 0) ? Aarg
                   : (L == 1) ? (const float*)d_H0
                   : (L == 2) ? (const float*)d_D1
                              : (const float*)d_H1;
    const float* Wb = (L <= 1) ? (Warg + (size_t)e * KD * ND)
                    : (L == 2) ? (d_W1T + (size_t)e * HID * HID)
                               : (d_W0T + (size_t)e * HID * INDIM);

    float acc[2][8][4];
#pragma unroll
    for (int mt = 0; mt < 2; mt++)
#pragma unroll
        for (int nt = 0; nt < 8; nt++)
#pragma unroll
            for (int j = 0; j < 4; j++) acc[mt][nt][j] = 0.f;

    const int arow = tid >> 1;           // 0..127
    const int ahalf = tid & 1;           // k offset 8*ahalf

    for (int k0 = 0; k0 < KD; k0 += 16) {
        __syncthreads();
        // ---- fill A (128 x 16) hi/lo, packed bf16x2 along k ----
        {
            const float* src;
            bool valid = true;
            if (L == 0) {
                int g = sPerm[arow];
                valid = (g >= 0);
                src = A + (size_t)(valid ? g : 0) * KD + k0 + ahalf * 8;
            } else {
                src = A + (size_t)(row0 + arow) * KD + k0 + ahalf * 8;
            }
#pragma unroll
            for (int j2 = 0; j2 < 2; j2++) {
                float4 v = valid ? *(const float4*)(src + 4 * j2)
                                 : make_float4(0.f, 0.f, 0.f, 0.f);
                int kp = ahalf * 4 + j2 * 2;
                split_pair(v.x, v.y, As_hi[arow][kp],     As_lo[arow][kp]);
                split_pair(v.z, v.w, As_hi[arow][kp + 1], As_lo[arow][kp + 1]);
            }
        }
        // ---- fill B: Bs[kp][n] = (W[k0+2kp][n], W[k0+2kp+1][n]) hi/lo ----
#pragma unroll
        for (int t = 0; t < 4; t++) {
            int idx = tid + t * 256;         // 0..1023
            int kp = idx >> 7;               // 0..7
            int n  = idx & 127;
            const float* s = Wb + (size_t)(k0 + 2 * kp) * ND + ncol0 + n;
            float x = s[0];
            float y = s[ND];
            split_pair(x, y, Bs_hi[kp][n], Bs_lo[kp][n]);
        }
        __syncthreads();

        // ---- fragments + 3-pass mma ----
        unsigned ah[2][4], al[2][4];
        const int kp = lane & 3;
#pragma unroll
        for (int mt = 0; mt < 2; mt++) {
            int m = wm * 32 + mt * 16 + (lane >> 2);
            ah[mt][0] = As_hi[m][kp];
            ah[mt][1] = As_hi[m + 8][kp];
            ah[mt][2] = As_hi[m][kp + 4];
            ah[mt][3] = As_hi[m + 8][kp + 4];
            al[mt][0] = As_lo[m][kp];
            al[mt][1] = As_lo[m + 8][kp];
            al[mt][2] = As_lo[m][kp + 4];
            al[mt][3] = As_lo[m + 8][kp + 4];
        }
#pragma unroll
        for (int nt = 0; nt < 8; nt++) {
            int n = wn * 64 + nt * 8 + (lane >> 2);
            unsigned bh0 = Bs_hi[kp][n];
            unsigned bh1 = Bs_hi[kp + 4][n];
            unsigned bl0 = Bs_lo[kp][n];
            unsigned bl1 = Bs_lo[kp + 4][n];
#pragma unroll
            for (int mt = 0; mt < 2; mt++) {
                mma16(acc[mt][nt], ah[mt], bh0, bh1);  // hi*hi
                mma16(acc[mt][nt], ah[mt], bl0, bl1);  // hi*lo
                mma16(acc[mt][nt], al[mt], bh0, bh1);  // lo*hi
            }
        }
    }

    // ---- epilogue ----
#pragma unroll
    for (int mt = 0; mt < 2; mt++) {
#pragma unroll
        for (int nt = 0; nt < 8; nt++) {
            float* cc = acc[mt][nt];
            int rloc = wm * 32 + mt * 16 + (lane >> 2);
            int c = ncol0 + wn * 64 + nt * 8 + (lane & 3) * 2;
            if (L == 0) {
                float2 b = *(const float2*)&dp_b0[e * ND + c];
                size_t r0i = (size_t)(row0 + rloc) * ND + c;
                size_t r1i = (size_t)(row0 + rloc + 8) * ND + c;
                d_H0[r0i]     = tanhf(cc[0] + b.x);
                d_H0[r0i + 1] = tanhf(cc[1] + b.y);
                d_H0[r1i]     = tanhf(cc[2] + b.x);
                d_H0[r1i + 1] = tanhf(cc[3] + b.y);
            } else if (L == 1) {
                float2 b = *(const float2*)&dp_b1[e * ND + c];
                size_t r0i = (size_t)(row0 + rloc) * ND + c;
                size_t r1i = (size_t)(row0 + rloc + 8) * ND + c;
                d_H1[r0i]     = tanhf(cc[0] + b.x);
                d_H1[r0i + 1] = tanhf(cc[1] + b.y);
                d_H1[r1i]     = tanhf(cc[2] + b.x);
                d_H1[r1i + 1] = tanhf(cc[3] + b.y);
            } else if (L == 2) {
                size_t r0i = (size_t)(row0 + rloc) * ND + c;
                size_t r1i = (size_t)(row0 + rloc + 8) * ND + c;
                float2 h0 = *(const float2*)&d_H0[r0i];
                float2 h1 = *(const float2*)&d_H0[r1i];
                d_H1[r0i]     = cc[0] * (1.f - h0.x * h0.x);
                d_H1[r0i + 1] = cc[1] * (1.f - h0.y * h0.y);
                d_H1[r1i]     = cc[2] * (1.f - h1.x * h1.x);
                d_H1[r1i + 1] = cc[3] * (1.f - h1.y * h1.y);
            } else {
                int a0 = sPerm[rloc];
                int a1 = sPerm[rloc + 8];
                if (a0 >= 0) {
                    d_G[(size_t)a0 * ND + c]     = cc[0];
                    d_G[(size_t)a0 * ND + c + 1] = cc[1];
                }
                if (a1 >= 0) {
                    d_G[(size_t)a1 * ND + c]     = cc[2];
                    d_G[(size_t)a1 * ND + c + 1] = cc[3];
                }
            }
        }
    }
}

// ---------------- layer2: energy + D1 ----------------
__global__ __launch_bounds__(256)
void k_layer2(const float* __restrict__ b2, float* __restrict__ energy) {
    int r = blockIdx.x;
    if (r >= d_off[NELEM]) return;
    int e = 0;
#pragma unroll
    for (int t = 0; t < NELEM - 1; t++)
        if (r >= d_off[t + 1]) e = t + 1;
    int tid = threadIdx.x;

    float h = d_H1[(size_t)r * HID + tid];
    float w = dp_w2[e * HID + tid];
    d_D1[(size_t)r * HID + tid] = w * (1.f - h * h);
    float p = h * w;

    __shared__ float sred[8];
#pragma unroll
    for (int o = 16; o > 0; o >>= 1) p += __shfl_down_sync(0xffffffffu, p, o);
    if ((tid & 31) == 0) sred[tid >> 5] = p;
    __syncthreads();
    if (tid == 0) {
        float s = 0.f;
#pragma unroll
        for (int k = 0; k < 8; k++) s += sred[k];
        int atom = d_perm[r];
        if (atom >= 0)
            atomicAdd(&energy[ld_idx(dp_img, atom, d_is64[0])], s + b2[e]);
    }
}

// ---------------- sparse transpose scatter ----------------
__global__ void k_sparse(float* __restrict__ out) {
    int i = blockIdx.x * blockDim.x + threadIdx.x;
    if (i < NNZV) {
        int is64 = d_is64[1];
        float g = d_G[ld_idx(dp_rows, i, is64)];
        atomicAdd(&out[NIMG + ld_idx(dp_cols, i, is64)], -dp_vals[i] * g);
    }
}

// ---------------- launch ----------------
extern "C" void kernel_launch(void* const* d_in, const int* in_sizes, int n_in,
                              void* d_out, int out_size) {
    int i_fp = 0, i_W0 = 6, i_W1 = 8, i_b2 = 11;
    int p50[2] = {1, 2};
    int p2M[3] = {3, 4, 5};
    int p1k[3] = {7, 9, 10};

    {
        int fp = -1, w0 = -1, w1 = -1, b2p = -1;
        int c50[2], n50 = 0, c2M[3], n2M = 0, c1k[3], n1k = 0;
        for (int i = 0; i < n_in; i++) {
            int s = in_sizes[i];
            if (s == 6400000) fp = i;
            else if (s == 131072) w0 = i;
            else if (s == 262144) w1 = i;
            else if (s == 4) b2p = i;
            else if (s == 50000 || s == 100000) { if (n50 < 2) c50[n50++] = i; }
            else if (s == 2000000 || s == 4000000) { if (n2M < 3) c2M[n2M++] = i; }
            else if (s == 1024) { if (n1k < 3) c1k[n1k++] = i; }
        }
        if (fp >= 0 && w0 >= 0 && w1 >= 0 && b2p >= 0 &&
            n50 == 2 && n2M == 3 && n1k == 3) {
            i_fp = fp; i_W0 = w0; i_W1 = w1; i_b2 = b2p;
            p50[0] = c50[0]; p50[1] = c50[1];
            p2M[0] = c2M[0]; p2M[1] = c2M[1]; p2M[2] = c2M[2];
            p1k[0] = c1k[0]; p1k[1] = c1k[1]; p1k[2] = c1k[2];
        }
    }

    const float* fp = (const float*)d_in[i_fp];
    const float* W0 = (const float*)d_in[i_W0];
    const float* W1 = (const float*)d_in[i_W1];
    const float* b2 = (const float*)d_in[i_b2];
    float* out = (float*)d_out;
    (void)out_size;

    k_detect<<<1, 256>>>((const int*)d_in[p50[0]], (const int*)d_in[p50[1]],
                         (const int*)d_in[p2M[0]], (const int*)d_in[p2M[1]],
                         (const int*)d_in[p2M[2]],
                         (const float*)d_in[p1k[0]], (const float*)d_in[p1k[1]],
                         (const float*)d_in[p1k[2]]);
    k_zero_out<<<512, 256>>>(out);
    k_reset<<<1, 32>>>();
    k_count<<<(NATOMS + 255) / 256, 256>>>();
    k_offsets<<<1, 32>>>();
    k_fillperm<<<(NPAD + 255) / 256, 256>>>();
    k_scatter<<<(NATOMS + 255) / 256, 256>>>();
    {
        int ntr = NELEM * HID * INDIM + NELEM * HID * HID;
        k_transpose<<<(ntr + 255) / 256, 256>>>(W0, W1);
    }

    dim3 gfull(NT128, 2);   // ND=256
    dim3 ghalf(NT128, 1);   // ND=128

    k_gemm_tc<0><<<gfull, 256>>>(fp, W0);           // H0
    k_gemm_tc<1><<<gfull, 256>>>(nullptr, W1);      // H1
    k_layer2<<<NPAD, 256>>>(b2, out);               // energy + D1
    k_gemm_tc<2><<<gfull, 256>>>(nullptr, nullptr); // D0
    k_gemm_tc<3><<<ghalf, 256>>>(nullptr, nullptr); // G scatter
    k_sparse<<<(NNZV + 255) / 256, 256>>>(out);     // forces
}

// round 10
// speedup vs baseline: 2.0015x; 1.1872x over previous
#include <cuda_runtime.h>
#include <cuda_bf16.h>
#include <cstdint>

#define NATOMS 50000
#define INDIM  128
#define HID    256
#define NELEM  4
#define NIMG   500
#define NNZV   2000000
#define NPAD   50560            // 395 * 128 >= NATOMS + 4*127
#define NT128  (NPAD / 128)     // 395
#define OUTSZ  (NIMG + 3 * NATOMS)

// ---------------- device scratch (referenced ONLY in device code) ----------
__device__ float d_H0[(size_t)NPAD * HID];
__device__ float d_H1[(size_t)NPAD * HID];   // D0 (L2 output, L3 input)
__device__ float d_D1[(size_t)NPAD * HID];
__device__ float d_G[(size_t)NATOMS * INDIM];
__device__ float d_rowE[NPAD];               // per padded-row energy partials
__device__ float d_W0T[NELEM * HID * INDIM]; // [e][h][d]
__device__ float d_W1T[NELEM * HID * HID];   // [e][j][i]
__device__ int   d_perm[NPAD];
__device__ int   d_cnt[NELEM];
__device__ int   d_cur[NELEM];
__device__ int   d_off[NELEM + 1];
__device__ int   d_is64[2];

__device__ const int*   dp_an;
__device__ const int*   dp_img;
__device__ const int*   dp_rows;
__device__ const int*   dp_cols;
__device__ const float* dp_vals;
__device__ const float* dp_b0;
__device__ const float* dp_b1;
__device__ const float* dp_w2;

__device__ __forceinline__ int ld_idx(const int* __restrict__ p, int i, int is64) {
    return p[is64 ? (2 * i) : i];
}
__device__ __forceinline__ int emap(int z) {
    return z == 1 ? 0 : (z == 6 ? 1 : (z == 8 ? 2 : 3));
}
__device__ __forceinline__ bool in_elem_set(int v) {
    return v == 1 || v == 6 || v == 8 || v == 29;
}
__device__ __forceinline__ unsigned bpack(float x, float y) {
    __nv_bfloat162 t = __floats2bfloat162_rn(x, y);
    return *reinterpret_cast<unsigned*>(&t);
}
__device__ __forceinline__ void split_pair(float x, float y,
                                           unsigned& hi, unsigned& lo) {
    float hx = __bfloat162float(__float2bfloat16(x));
    float hy = __bfloat162float(__float2bfloat16(y));
    hi = bpack(hx, hy);
    lo = bpack(x - hx, y - hy);
}
__device__ __forceinline__ void mma16(float* c, const unsigned* a,
                                      unsigned b0, unsigned b1) {
    asm volatile(
        "mma.sync.aligned.m16n8k16.row.col.f32.bf16.bf16.f32 "
        "{%0,%1,%2,%3}, {%4,%5,%6,%7}, {%8,%9}, {%0,%1,%2,%3};"
        : "+f"(c[0]), "+f"(c[1]), "+f"(c[2]), "+f"(c[3])
        : "r"(a[0]), "r"(a[1]), "r"(a[2]), "r"(a[3]), "r"(b0), "r"(b1));
}

// ---------------- input identification (+ counter reset) ----------------
__global__ void k_detect(const int* pa, const int* pb,
                         const int* q0, const int* q1, const int* q2,
                         const float* r0, const float* r1, const float* r2) {
    __shared__ int s_anfail[2];
    __shared__ int s_isf[3];
    __shared__ int s_qmax[3];
    __shared__ int s_bmax[3];
    int tid = threadIdx.x;
    if (tid < 2) s_anfail[tid] = 0;
    if (tid < 3) { s_isf[tid] = 0; s_qmax[tid] = 0; s_bmax[tid] = 0; }
    if (tid < NELEM) { d_cnt[tid] = 0; d_cur[tid] = 0; }
    __syncthreads();

    const int* pp[2] = {pa, pb};
    const int* qq[3] = {q0, q1, q2};
    const float* rr[3] = {r0, r1, r2};

    if (tid < 32) {
        int c = tid >> 4;
        int i = tid & 15;
        if (!in_elem_set(pp[c][2 * i])) atomicExch(&s_anfail[c], 1);
    }
    for (int j = 0; j < 3; j++) {
        const int* q = qq[j];
        for (int i = tid; i < 1024; i += blockDim.x) {
            int w = q[i];
            if (w < 0 || w > 0x30000000) atomicExch(&s_isf[j], 1);
            atomicMax(&s_qmax[j], w);
        }
    }
    for (int j = 0; j < 3; j++) {
        const float* r = rr[j];
        for (int i = tid; i < 1024; i += blockDim.x) {
            float v = fabsf(r[i]);
            atomicMax(&s_bmax[j], __float_as_int(v));
        }
    }
    __syncthreads();

    if (tid == 0) {
        int asel = s_anfail[0] ? (s_anfail[1] ? 0 : 1) : 0;
        dp_an  = pp[asel];
        dp_img = pp[1 - asel];
        d_is64[0] = (pp[asel][1] == 0 && pp[asel][3] == 0 && pp[asel][5] == 0) ? 1 : 0;

        int vsel = 2;
        if (s_isf[0]) vsel = 0; else if (s_isf[1]) vsel = 1; else if (s_isf[2]) vsel = 2;
        int o1 = (vsel == 0) ? 1 : 0;
        int o2 = (vsel == 2) ? 1 : 2;
        int rsel = (s_qmax[o1] >= s_qmax[o2]) ? o1 : o2;
        int csel = o1 + o2 - rsel;
        dp_vals = (const float*)qq[vsel];
        dp_rows = qq[rsel];
        dp_cols = qq[csel];
        const int* rw = qq[rsel];
        d_is64[1] = (rw[1] == 0 && rw[3] == 0 && rw[5] == 0 && rw[7] == 0 &&
                     rw[9] == 0 && rw[11] == 0) ? 1 : 0;

        int b0s;
        if (s_bmax[0] >= s_bmax[1] && s_bmax[0] >= s_bmax[2]) b0s = 0;
        else if (s_bmax[1] >= s_bmax[2]) b0s = 1;
        else b0s = 2;
        int b1s = (b0s + 1) % 3;
        int w2s = (b0s + 2) % 3;
        dp_b0 = rr[b0s]; dp_b1 = rr[b1s]; dp_w2 = rr[w2s];
    }
}

// ---------------- zero/init: out, perm, rowE ----------------
__global__ void k_zero_init(float* out) {
    int i = blockIdx.x * blockDim.x + threadIdx.x;
    if (i < OUTSZ) out[i] = 0.f;
    if (i < NPAD) { d_perm[i] = -1; d_rowE[i] = 0.f; }
}

__global__ void k_count() {
    __shared__ int sc[NELEM];
    int tid = threadIdx.x;
    if (tid < NELEM) sc[tid] = 0;
    __syncthreads();
    int i = blockIdx.x * blockDim.x + tid;
    if (i < NATOMS) atomicAdd(&sc[emap(ld_idx(dp_an, i, d_is64[0]))], 1);
    __syncthreads();
    if (tid < NELEM && sc[tid] > 0) atomicAdd(&d_cnt[tid], sc[tid]);
}

__global__ void k_offsets() {
    if (threadIdx.x == 0 && blockIdx.x == 0) {
        int o = 0;
        for (int e = 0; e < NELEM; e++) {
            d_off[e] = o;
            o += ((d_cnt[e] + 127) / 128) * 128;
        }
        d_off[NELEM] = o;
    }
}

__global__ void k_scatter() {
    __shared__ int lc[NELEM], base[NELEM];
    int tid = threadIdx.x;
    if (tid < NELEM) lc[tid] = 0;
    __syncthreads();
    int i = blockIdx.x * blockDim.x + tid;
    int e = -1, rank = 0;
    if (i < NATOMS) {
        e = emap(ld_idx(dp_an, i, d_is64[0]));
        rank = atomicAdd(&lc[e], 1);
    }
    __syncthreads();
    if (tid < NELEM && lc[tid] > 0) base[tid] = atomicAdd(&d_cur[tid], lc[tid]);
    __syncthreads();
    if (i < NATOMS) d_perm[d_off[e] + base[e] + rank] = i;
}

__global__ void k_transpose(const float* __restrict__ W0,
                            const float* __restrict__ W1) {
    const int n0 = NELEM * HID * INDIM;
    const int n1 = NELEM * HID * HID;
    int i = blockIdx.x * blockDim.x + threadIdx.x;
    if (i < n0) {
        int d = i % INDIM;
        int t = i / INDIM;
        int h = t % HID;
        int e = t / HID;
        d_W0T[i] = W0[((size_t)e * INDIM + d) * HID + h];
    } else if (i < n0 + n1) {
        int k = i - n0;
        int i2 = k % HID;
        int t = k / HID;
        int j = t % HID;
        int e = t / HID;
        d_W1T[k] = W1[((size_t)e * HID + i2) * HID + j];
    }
}

// ---------------- BF16x3 tensor-core GEMM, register-prefetch pipelined ------
// L=0: H0 = tanh(FP[perm] @ W0 + b0)                       KD=128 ND=256
// L=1: D1 = w2*(1-h1^2), rowE partial (h1 never stored)    KD=256 ND=256
// L=2: D0 = (D1 @ W1T) * (1 - H0^2) -> d_H1                KD=256 ND=256
// L=3: G[perm[r]] = D0 @ W0T (scatter)                     KD=256 ND=128
#define SAN 20
#define SBN 136

template <int L>
__global__ __launch_bounds__(256)
void k_gemm_tc(const float* __restrict__ Aarg, const float* __restrict__ Warg) {
    constexpr int KD = (L == 0) ? INDIM : HID;
    constexpr int ND = (L == 3) ? INDIM : HID;

    const int row0 = blockIdx.x * 128;
    if (row0 >= d_off[NELEM]) return;
    int e = 0;
#pragma unroll
    for (int t = 0; t < NELEM - 1; t++)
        if (row0 >= d_off[t + 1]) e = t + 1;
    const int ncol0 = blockIdx.y * 128;

    __shared__ unsigned As_hi[128][SAN], As_lo[128][SAN];
    __shared__ unsigned Bs_hi[8][SBN],  Bs_lo[8][SBN];
    __shared__ int sPerm[128];
    __shared__ float s_row[128];

    const int tid  = threadIdx.x;
    const int lane = tid & 31;
    const int wid  = tid >> 5;
    const int wm   = wid & 3;
    const int wn   = wid >> 2;

    if (tid < 128) {
        sPerm[tid] = d_perm[row0 + tid];
        if (L == 1) s_row[tid] = 0.f;
    }
    __syncthreads();

    const float* A = (L == 0) ? Aarg
                   : (L == 1) ? (const float*)d_H0
                   : (L == 2) ? (const float*)d_D1
                              : (const float*)d_H1;
    const float* Wb = (L <= 1) ? (Warg + (size_t)e * KD * ND)
                    : (L == 2) ? (d_W1T + (size_t)e * HID * HID)
                               : (d_W0T + (size_t)e * HID * INDIM);

    float acc[2][8][4];
#pragma unroll
    for (int mt = 0; mt < 2; mt++)
#pragma unroll
        for (int nt = 0; nt < 8; nt++)
#pragma unroll
            for (int j = 0; j < 4; j++) acc[mt][nt][j] = 0.f;

    const int arow  = tid >> 1;
    const int ahalf = tid & 1;

    // prefetch registers
    float4 avA[2];
    float bxv[4], byv[4];
    bool avalid = true;

    // ---- preload chunk 0 ----
    {
        if (L == 0) {
            int g = sPerm[arow];
            avalid = (g >= 0);
            const float* src = A + (size_t)(avalid ? g : 0) * KD + ahalf * 8;
            avA[0] = avalid ? *(const float4*)(src)     : make_float4(0,0,0,0);
            avA[1] = avalid ? *(const float4*)(src + 4) : make_float4(0,0,0,0);
        } else {
            const float* src = A + (size_t)(row0 + arow) * KD + ahalf * 8;
            avA[0] = *(const float4*)(src);
            avA[1] = *(const float4*)(src + 4);
        }
#pragma unroll
        for (int t = 0; t < 4; t++) {
            int idx = tid + t * 256;
            int kp = idx >> 7;
            int n  = idx & 127;
            const float* s = Wb + (size_t)(2 * kp) * ND + ncol0 + n;
            bxv[t] = s[0];
            byv[t] = s[ND];
        }
    }

    for (int k0 = 0; k0 < KD; k0 += 16) {
        __syncthreads();
        // ---- store current chunk (split to hi/lo) ----
#pragma unroll
        for (int j2 = 0; j2 < 2; j2++) {
            int kp = ahalf * 4 + j2 * 2;
            float4 v = avA[j2];
            split_pair(v.x, v.y, As_hi[arow][kp],     As_lo[arow][kp]);
            split_pair(v.z, v.w, As_hi[arow][kp + 1], As_lo[arow][kp + 1]);
        }
#pragma unroll
        for (int t = 0; t < 4; t++) {
            int idx = tid + t * 256;
            int kp = idx >> 7;
            int n  = idx & 127;
            split_pair(bxv[t], byv[t], Bs_hi[kp][n], Bs_lo[kp][n]);
        }
        __syncthreads();

        // ---- preload next chunk while mma runs ----
        if (k0 + 16 < KD) {
            int kn = k0 + 16;
            if (L == 0) {
                const float* src = A + (size_t)(avalid ? sPerm[arow] : 0) * KD
                                   + kn + ahalf * 8;
                avA[0] = avalid ? *(const float4*)(src)     : make_float4(0,0,0,0);
                avA[1] = avalid ? *(const float4*)(src + 4) : make_float4(0,0,0,0);
            } else {
                const float* src = A + (size_t)(row0 + arow) * KD + kn + ahalf * 8;
                avA[0] = *(const float4*)(src);
                avA[1] = *(const float4*)(src + 4);
            }
#pragma unroll
            for (int t = 0; t < 4; t++) {
                int idx = tid + t * 256;
                int kp = idx >> 7;
                int n  = idx & 127;
                const float* s = Wb + (size_t)(kn + 2 * kp) * ND + ncol0 + n;
                bxv[t] = s[0];
                byv[t] = s[ND];
            }
        }

        // ---- fragments + 3-pass mma ----
        unsigned ah[2][4], al[2][4];
        const int kp = lane & 3;
#pragma unroll
        for (int mt = 0; mt < 2; mt++) {
            int m = wm * 32 + mt * 16 + (lane >> 2);
            ah[mt][0] = As_hi[m][kp];
            ah[mt][1] = As_hi[m + 8][kp];
            ah[mt][2] = As_hi[m][kp + 4];
            ah[mt][3] = As_hi[m + 8][kp + 4];
            al[mt][0] = As_lo[m][kp];
            al[mt][1] = As_lo[m + 8][kp];
            al[mt][2] = As_lo[m][kp + 4];
            al[mt][3] = As_lo[m + 8][kp + 4];
        }
#pragma unroll
        for (int nt = 0; nt < 8; nt++) {
            int n = wn * 64 + nt * 8 + (lane >> 2);
            unsigned bh0 = Bs_hi[kp][n];
            unsigned bh1 = Bs_hi[kp + 4][n];
            unsigned bl0 = Bs_lo[kp][n];
            unsigned bl1 = Bs_lo[kp + 4][n];
#pragma unroll
            for (int mt = 0; mt < 2; mt++) {
                mma16(acc[mt][nt], ah[mt], bh0, bh1);
                mma16(acc[mt][nt], ah[mt], bl0, bl1);
                mma16(acc[mt][nt], al[mt], bh0, bh1);
            }
        }
    }

    // ---- epilogue ----
    float erow[2][2];   // L==1: per-thread energy partials [mt][row half]
    if (L == 1) {
        erow[0][0] = erow[0][1] = erow[1][0] = erow[1][1] = 0.f;
    }
#pragma unroll
    for (int mt = 0; mt < 2; mt++) {
#pragma unroll
        for (int nt = 0; nt < 8; nt++) {
            float* cc = acc[mt][nt];
            int rloc = wm * 32 + mt * 16 + (lane >> 2);
            int c = ncol0 + wn * 64 + nt * 8 + (lane & 3) * 2;
            if (L == 0) {
                float2 b = *(const float2*)&dp_b0[e * ND + c];
                size_t r0i = (size_t)(row0 + rloc) * ND + c;
                size_t r1i = (size_t)(row0 + rloc + 8) * ND + c;
                d_H0[r0i]     = tanhf(cc[0] + b.x);
                d_H0[r0i + 1] = tanhf(cc[1] + b.y);
                d_H0[r1i]     = tanhf(cc[2] + b.x);
                d_H0[r1i + 1] = tanhf(cc[3] + b.y);
            } else if (L == 1) {
                float2 b = *(const float2*)&dp_b1[e * ND + c];
                float2 w = *(const float2*)&dp_w2[e * ND + c];
                size_t r0i = (size_t)(row0 + rloc) * ND + c;
                size_t r1i = (size_t)(row0 + rloc + 8) * ND + c;
                float h0 = tanhf(cc[0] + b.x);
                float h1 = tanhf(cc[1] + b.y);
                float h2 = tanhf(cc[2] + b.x);
                float h3 = tanhf(cc[3] + b.y);
                d_D1[r0i]     = w.x * (1.f - h0 * h0);
                d_D1[r0i + 1] = w.y * (1.f - h1 * h1);
                d_D1[r1i]     = w.x * (1.f - h2 * h2);
                d_D1[r1i + 1] = w.y * (1.f - h3 * h3);
                erow[mt][0] += h0 * w.x + h1 * w.y;
                erow[mt][1] += h2 * w.x + h3 * w.y;
            } else if (L == 2) {
                size_t r0i = (size_t)(row0 + rloc) * ND + c;
                size_t r1i = (size_t)(row0 + rloc + 8) * ND + c;
                float2 h0 = *(const float2*)&d_H0[r0i];
                float2 h1 = *(const float2*)&d_H0[r1i];
                d_H1[r0i]     = cc[0] * (1.f - h0.x * h0.x);
                d_H1[r0i + 1] = cc[1] * (1.f - h0.y * h0.y);
                d_H1[r1i]     = cc[2] * (1.f - h1.x * h1.x);
                d_H1[r1i + 1] = cc[3] * (1.f - h1.y * h1.y);
            } else {
                int a0 = sPerm[rloc];
                int a1 = sPerm[rloc + 8];
                if (a0 >= 0) {
                    d_G[(size_t)a0 * ND + c]     = cc[0];
                    d_G[(size_t)a0 * ND + c + 1] = cc[1];
                }
                if (a1 >= 0) {
                    d_G[(size_t)a1 * ND + c]     = cc[2];
                    d_G[(size_t)a1 * ND + c + 1] = cc[3];
                }
            }
        }
    }

    if (L == 1) {
        // reduce 4 lanes covering the same row, then shared, then global
#pragma unroll
        for (int mt = 0; mt < 2; mt++)
#pragma unroll
            for (int h = 0; h < 2; h++) {
                float v = erow[mt][h];
                v += __shfl_xor_sync(0xffffffffu, v, 1);
                v += __shfl_xor_sync(0xffffffffu, v, 2);
                if ((lane & 3) == 0) {
                    int rloc = wm * 32 + mt * 16 + (lane >> 2) + h * 8;
                    atomicAdd(&s_row[rloc], v);
                }
            }
        __syncthreads();
        if (tid < 128) atomicAdd(&d_rowE[row0 + tid], s_row[tid]);
    }
}

// ---------------- energy segment sum ----------------
__global__ void k_energy(const float* __restrict__ b2, float* __restrict__ out) {
    int r = blockIdx.x * blockDim.x + threadIdx.x;
    if (r >= NPAD || r >= d_off[NELEM]) return;
    int atom = d_perm[r];
    if (atom < 0) return;
    int e = 0;
#pragma unroll
    for (int t = 0; t < NELEM - 1; t++)
        if (r >= d_off[t + 1]) e = t + 1;
    atomicAdd(&out[ld_idx(dp_img, atom, d_is64[0])], d_rowE[r] + b2[e]);
}

// ---------------- sparse transpose scatter ----------------
__global__ void k_sparse(float* __restrict__ out) {
    int i = blockIdx.x * blockDim.x + threadIdx.x;
    if (i < NNZV) {
        int is64 = d_is64[1];
        float g = d_G[ld_idx(dp_rows, i, is64)];
        atomicAdd(&out[NIMG + ld_idx(dp_cols, i, is64)], -dp_vals[i] * g);
    }
}

// ---------------- launch ----------------
extern "C" void kernel_launch(void* const* d_in, const int* in_sizes, int n_in,
                              void* d_out, int out_size) {
    int i_fp = 0, i_W0 = 6, i_W1 = 8, i_b2 = 11;
    int p50[2] = {1, 2};
    int p2M[3] = {3, 4, 5};
    int p1k[3] = {7, 9, 10};

    {
        int fp = -1, w0 = -1, w1 = -1, b2p = -1;
        int c50[2], n50 = 0, c2M[3], n2M = 0, c1k[3], n1k = 0;
        for (int i = 0; i < n_in; i++) {
            int s = in_sizes[i];
            if (s == 6400000) fp = i;
            else if (s == 131072) w0 = i;
            else if (s == 262144) w1 = i;
            else if (s == 4) b2p = i;
            else if (s == 50000 || s == 100000) { if (n50 < 2) c50[n50++] = i; }
            else if (s == 2000000 || s == 4000000) { if (n2M < 3) c2M[n2M++] = i; }
            else if (s == 1024) { if (n1k < 3) c1k[n1k++] = i; }
        }
        if (fp >= 0 && w0 >= 0 && w1 >= 0 && b2p >= 0 &&
            n50 == 2 && n2M == 3 && n1k == 3) {
            i_fp = fp; i_W0 = w0; i_W1 = w1; i_b2 = b2p;
            p50[0] = c50[0]; p50[1] = c50[1];
            p2M[0] = c2M[0]; p2M[1] = c2M[1]; p2M[2] = c2M[2];
            p1k[0] = c1k[0]; p1k[1] = c1k[1]; p1k[2] = c1k[2];
        }
    }

    const float* fp = (const float*)d_in[i_fp];
    const float* W0 = (const float*)d_in[i_W0];
    const float* W1 = (const float*)d_in[i_W1];
    const float* b2 = (const float*)d_in[i_b2];
    float* out = (float*)d_out;
    (void)out_size;

    k_detect<<<1, 256>>>((const int*)d_in[p50[0]], (const int*)d_in[p50[1]],
                         (const int*)d_in[p2M[0]], (const int*)d_in[p2M[1]],
                         (const int*)d_in[p2M[2]],
                         (const float*)d_in[p1k[0]], (const float*)d_in[p1k[1]],
                         (const float*)d_in[p1k[2]]);
    k_zero_init<<<(OUTSZ + 255) / 256, 256>>>(out);
    k_count<<<(NATOMS + 255) / 256, 256>>>();
    k_offsets<<<1, 32>>>();
    k_scatter<<<(NATOMS + 255) / 256, 256>>>();
    {
        int ntr = NELEM * HID * INDIM + NELEM * HID * HID;
        k_transpose<<<(ntr + 255) / 256, 256>>>(W0, W1);
    }

    dim3 gfull(NT128, 2);   // ND=256
    dim3 ghalf(NT128, 1);   // ND=128

    k_gemm_tc<0><<<gfull, 256>>>(fp, W0);            // H0
    k_gemm_tc<1><<<gfull, 256>>>(nullptr, W1);       // D1 + rowE (fused layer2)
    k_energy<<<(NPAD + 255) / 256, 256>>>(b2, out);  // energy segment sum
    k_gemm_tc<2><<<gfull, 256>>>(nullptr, nullptr);  // D0
    k_gemm_tc<3><<<ghalf, 256>>>(nullptr, nullptr);  // G scatter
    k_sparse<<<(NNZV + 255) / 256, 256>>>(out);      // forces
}